// round 2
// baseline (speedup 1.0000x reference)
#include <cuda_runtime.h>
#include <math.h>

#define BATCH 8
#define CHN   16
#define NN    64
#define KT    12
#define KXY   24
#define N3INV (1.0f/262144.0f)

// ---------------- scratch (static device memory; no allocations) ----------------
__device__ float2 g_Bf[BATCH*CHN*NN*KXY*KT];    // 2,359,296 c  (fwd: after Y-DFT; inv: after inv-X)
__device__ float2 g_D [BATCH*CHN*KXY*KXY*KT];   //   884,736 c  (spectral-multiplied modes)
__device__ float2 g_W [KXY*KXY*KT*CHN*CHN];     // 1,769,472 c  (repacked weights, mode-major)
__device__ float2 g_twT2 [KT*32];               // fwd T twiddle  (cos,sin) over t1<32
__device__ float2 g_twXY2[KXY*32];              // X/Y twiddle for 24 kept freqs over 32
__device__ float2 g_twTi2[KT*32];               // inv-T table (A,B) with 1/N^3, 2x folded

// ---------------- f32x2 packed helpers ----------------
__device__ __forceinline__ unsigned long long pk2(float lo, float hi){
    unsigned long long r; asm("mov.b64 %0, {%1,%2};" : "=l"(r) : "f"(lo), "f"(hi)); return r;
}
__device__ __forceinline__ void fma2(unsigned long long& d, unsigned long long a, unsigned long long b){
    asm("fma.rn.f32x2 %0, %1, %2, %0;" : "+l"(d) : "l"(a), "l"(b));
}
__device__ __forceinline__ float2 unpk2(unsigned long long v){
    float2 f; asm("mov.b64 {%0,%1}, %2;" : "=f"(f.x), "=f"(f.y) : "l"(v)); return f;
}

// ---------------- init: twiddle tables (rebuilt every launch) ----------------
__global__ void k_init() {
    int idx = blockIdx.x * blockDim.x + threadIdx.x;
    if (idx < 384) {
        int k = idx >> 5, t = idx & 31;
        int m = (k * t) & 63;
        float s, c;
        sincospif((float)m / 32.0f, &s, &c);
        g_twT2[idx] = make_float2(c, s);
        g_twTi2[idx] = (k == 0) ? make_float2(N3INV, 0.0f)
                                : make_float2(2.0f*c*N3INV, -2.0f*s*N3INV);
    } else if (idx < 384 + 768) {
        int r = idx - 384;
        int j = r >> 5, t = r & 31;
        int f = (j < 12) ? j : j + 40;   // freqs 0..11, 52..63
        int m = (f * t) & 63;
        float s, c;
        sincospif((float)m / 32.0f, &s, &c);
        g_twXY2[r] = make_float2(c, s);
    }
}

// ---------------- repack w1..w4 -> g_W[(kx*24+ky)*12+kz][i][o] ----------------
__global__ void k_repack(const float* __restrict__ w1, const float* __restrict__ w2,
                         const float* __restrict__ w3, const float* __restrict__ w4) {
    int idx = blockIdx.x * blockDim.x + threadIdx.x;
    if (idx >= KXY*KXY*KT*CHN*CHN) return;
    int o = idx & 15;
    int i = (idx >> 4) & 15;
    int r = idx >> 8;                   // (kxi*24+kyi)*12+kz
    int kz  = r % 12;  r /= 12;
    int kyi = r % 24;
    int kxi = r / 24;
    int jx = (kxi < 12) ? kxi : kxi - 12;
    int jy = (kyi < 12) ? kyi : kyi - 12;
    const float* w = (kxi < 12) ? ((kyi < 12) ? w1 : w3)
                                : ((kyi < 12) ? w2 : w4);
    int src = (i*16 + o)*1728 + (jx*12 + jy)*12 + kz;
    g_W[idx] = reinterpret_cast<const float2*>(w)[src];
}

// ---------------- KA: fused T-DFT (radix-2, 64->12) + Y-DFT (radix-2, 64->24) ----------------
// one block per slab (b,c,x); 128 threads
__global__ void __launch_bounds__(128) kA(const float* __restrict__ x) {
    __shared__ float  sx[64*65];        // input tile [y][t] padded; reused for Y EO buffer
    __shared__ float2 sA[64*13];        // T-DFT output [y][kz] (pad 13)
    __shared__ float2 stT[KT*32];
    __shared__ float2 stY[KXY*32];
    int slab = blockIdx.x;              // (b*16+c)*64+xx
    int tid = threadIdx.x;

    const float4* xs = (const float4*)(x + (size_t)slab * 4096);
    for (int i = tid; i < 1024; i += 128) {
        float4 v = xs[i];
        int yy = i >> 4, t4 = (i & 15) * 4;
        float* row = &sx[yy*65 + t4];
        row[0] = v.x; row[1] = v.y; row[2] = v.z; row[3] = v.w;
    }
    for (int i = tid; i < 384; i += 128) stT[i] = g_twT2[i];
    for (int i = tid; i < 768; i += 128) stY[i] = g_twXY2[i];
    __syncthreads();

    // radix-2 prep over t (in place): E at [t1], O at [t1+32]
    for (int i = tid; i < 2048; i += 128) {
        int yy = i >> 5, t1 = i & 31;
        float a = sx[yy*65 + t1], b = sx[yy*65 + t1 + 32];
        sx[yy*65 + t1]      = a + b;
        sx[yy*65 + t1 + 32] = a - b;
    }
    __syncthreads();

    // T-DFT stage2: thread = (y, half of kz)
    {
        int yy = tid & 63, g = tid >> 6;   // kz = 6g .. 6g+5
        const float* row = &sx[yy*65];
        float ar[6], ai[6];
#pragma unroll
        for (int j = 0; j < 6; j++) { ar[j] = 0.f; ai[j] = 0.f; }
#pragma unroll 4
        for (int t1 = 0; t1 < 32; t1++) {
            float E = row[t1], O = row[t1 + 32];
#pragma unroll
            for (int j = 0; j < 6; j++) {
                int k = g*6 + j;
                float v = (k & 1) ? O : E;
                float2 w = stT[k*32 + t1];     // warp-uniform -> broadcast
                ar[j] += v * w.x;
                ai[j] -= v * w.y;
            }
        }
#pragma unroll
        for (int j = 0; j < 6; j++) sA[yy*13 + g*6 + j] = make_float2(ar[j], ai[j]);
    }
    __syncthreads();

    // radix-2 prep over y into reused sx buffer: E at [i], O at [384+i], i = y1*12+k
    float2* sEO = (float2*)sx;
    for (int i = tid; i < 384; i += 128) {
        int y1 = i / 12, k = i % 12;
        float2 a = sA[y1*13 + k], b = sA[(y1+32)*13 + k];
        sEO[i]       = make_float2(a.x + b.x, a.y + b.y);
        sEO[384 + i] = make_float2(a.x - b.x, a.y - b.y);
    }
    __syncthreads();

    // Y-DFT stage2: 96 threads: thread = (ky, kz-triple)
    if (tid < 96) {
        int ky = tid >> 2, q = tid & 3, k0 = q*3;
        const float2* rowp = sEO + (ky & 1) * 384;
        float2 acc[3];
#pragma unroll
        for (int j = 0; j < 3; j++) acc[j] = make_float2(0.f, 0.f);
#pragma unroll 4
        for (int y1 = 0; y1 < 32; y1++) {
            float2 w = stY[ky*32 + y1];
#pragma unroll
            for (int j = 0; j < 3; j++) {
                float2 a = rowp[y1*12 + k0 + j];
                acc[j].x += a.x*w.x + a.y*w.y;   // * e^{-i th}
                acc[j].y += a.y*w.x - a.x*w.y;
            }
        }
        float2* dst = g_Bf + (size_t)slab*288 + ky*12 + k0;
#pragma unroll
        for (int j = 0; j < 3; j++) dst[j] = acc[j];
    }
}

// ---------------- KB: X-DFT (radix-2, 64->24) fused with spectral 16x16 mix ----------------
// block = (b, ky, kz); 384 threads
__global__ void __launch_bounds__(384) kB() {
    __shared__ float2 sIn[CHN*65];     // [c][x], padded; EO in place
    __shared__ float2 sAcc[KXY*CHN];   // a-hat[kx][c]
    __shared__ float2 stX[KXY*32];
    int blk = blockIdx.x;
    int b  = blk / 288;
    int r  = blk % 288;
    int ky = r / 12, kz = r % 12;
    int tid = threadIdx.x;

    for (int i = tid; i < 1024; i += 384) {
        int c = i >> 6, xx = i & 63;
        sIn[c*65 + xx] = g_Bf[(((size_t)(b*16 + c)*64 + xx)*24 + ky)*12 + kz];
    }
    for (int i = tid; i < 768; i += 384) stX[i] = g_twXY2[i];
    __syncthreads();

    for (int i = tid; i < 512; i += 384) {
        int c = i >> 5, x1 = i & 31;
        float2 a = sIn[c*65 + x1], bb = sIn[c*65 + x1 + 32];
        sIn[c*65 + x1]      = make_float2(a.x + bb.x, a.y + bb.y);
        sIn[c*65 + x1 + 32] = make_float2(a.x - bb.x, a.y - bb.y);
    }
    __syncthreads();

    {   // stage 1: X DFT -> sAcc[kx][c]
        int kx = tid >> 4, c = tid & 15;
        const float2* rowp = &sIn[c*65 + (kx & 1)*32];
        const float2* tw = &stX[kx*32];
        float2 acc = make_float2(0.f, 0.f);
#pragma unroll 4
        for (int x1 = 0; x1 < 32; x1++) {
            float2 w = tw[x1]; float2 v = rowp[x1];
            acc.x += v.x*w.x + v.y*w.y;
            acc.y += v.y*w.x - v.x*w.y;
        }
        sAcc[kx*16 + c] = acc;
    }
    __syncthreads();
    {   // stage 2: per-mode complex channel mix, write D[b][o][ky][kx][kz]
        int kx = tid >> 4, o = tid & 15;
        const float2* Wp = g_W + ((size_t)((kx*24 + ky)*12 + kz)) * 256;
        float2 acc = make_float2(0.f, 0.f);
#pragma unroll
        for (int i = 0; i < 16; i++) {
            float2 av = sAcc[kx*16 + i];
            float2 w  = Wp[i*16 + o];
            acc.x += av.x*w.x - av.y*w.y;
            acc.y += av.x*w.y + av.y*w.x;
        }
        g_D[(((size_t)(b*16 + o)*24 + ky)*24 + kx)*12 + kz] = acc;
    }
}

// ---------------- KC: inverse X DFT (24 kept bins -> 64), parity decimation ----------------
// block = (bo, ky); 384 threads; thread = (kz, x1)
__global__ void __launch_bounds__(384) kC() {
    __shared__ float2 sD[KXY*KT];
    __shared__ float2 stX[KXY*32];
    int blk = blockIdx.x;              // bo*24 + ky
    int tid = threadIdx.x;
    for (int i = tid; i < 288; i += 384) sD[i] = g_D[(size_t)blk*288 + i];
    for (int i = tid; i < 768; i += 384) stX[i] = g_twXY2[i];
    __syncthreads();

    int kz = tid >> 5, x1 = tid & 31;
    float2 Se = make_float2(0.f, 0.f), So = make_float2(0.f, 0.f);
#pragma unroll
    for (int kx = 0; kx < 24; kx++) {
        float2 w = stX[kx*32 + x1];
        float2 d = sD[kx*12 + kz];
        float tr = d.x*w.x - d.y*w.y;    // * e^{+i th}
        float ti = d.x*w.y + d.y*w.x;
        if (kx & 1) { So.x += tr; So.y += ti; }
        else        { Se.x += tr; Se.y += ti; }
    }
    int bo = blk / 24, ky = blk % 24;
    float2* base = g_Bf + ((size_t)bo*64)*288 + ky*12 + kz;
    base[(size_t)x1*288]        = make_float2(Se.x + So.x, Se.y + So.y);
    base[(size_t)(x1+32)*288]   = make_float2(Se.x - So.x, Se.y - So.y);
}

// ---------------- KD: fused inverse-Y + inverse-T + ReLU + 16x16 mix + bias ----------------
// block = (b, x); 512 threads; dynamic smem
#define KD_THREADS 512
#define KD_SMEM ((4608 + 13312 + 768 + 384)*8 + 256*8 + 16*4)
__global__ void __launch_bounds__(KD_THREADS) kD(const float* __restrict__ lo_w,
                                                 const float* __restrict__ lo_b,
                                                 float* __restrict__ out) {
    extern __shared__ char smemraw[];
    float2* sE  = (float2*)smemraw;          // 16*288
    float2* sF  = sE + 4608;                 // 16*64*13 (pad 13)
    float2* stY = sF + 13312;                // 24*32
    float2* sTi = stY + 768;                 // 12*32
    unsigned long long* sWq = (unsigned long long*)(sTi + 384);  // 256 dup-packed
    float* sB = (float*)(sWq + 256);         // 16
    int tid = threadIdx.x;
    int b = blockIdx.x >> 6, xx = blockIdx.x & 63;

    for (int i = tid; i < 4608; i += KD_THREADS) {
        int c = i / 288, r = i % 288;
        sE[i] = g_Bf[(((size_t)(b*16 + c)*64) + xx)*288 + r];
    }
    for (int i = tid; i < 768; i += KD_THREADS) stY[i] = g_twXY2[i];
    for (int i = tid; i < 384; i += KD_THREADS) sTi[i] = g_twTi2[i];
    if (tid < 256) { float w = lo_w[tid]; sWq[tid] = pk2(w, w); }
    if (tid < 16)  sB[tid] = lo_b[tid];
    __syncthreads();

    // phase 1: inverse Y with parity decimation; thread = (c, y1)
    {
        int c = tid >> 5, y1 = tid & 31;
        float2 Se[12], So[12];
#pragma unroll
        for (int k = 0; k < 12; k++) { Se[k] = make_float2(0,0); So[k] = make_float2(0,0); }
        const float2* Ebase = sE + c*288;
#pragma unroll 2
        for (int ky = 0; ky < 24; ky++) {
            float2 w = stY[ky*32 + y1];
            const float2* dk = Ebase + ky*12;
#pragma unroll
            for (int k = 0; k < 12; k++) {
                float2 d = dk[k];
                float tr = d.x*w.x - d.y*w.y;
                float ti = d.x*w.y + d.y*w.x;
                if (ky & 1) { So[k].x += tr; So[k].y += ti; }
                else        { Se[k].x += tr; Se[k].y += ti; }
            }
        }
        float2* f0 = sF + (c*64 + y1)*13;
        float2* f1 = sF + (c*64 + y1 + 32)*13;
#pragma unroll
        for (int k = 0; k < 12; k++) {
            f0[k] = make_float2(Se[k].x + So[k].x, Se[k].y + So[k].y);
            f1[k] = make_float2(Se[k].x - So[k].x, Se[k].y - So[k].y);
        }
    }
    __syncthreads();

    // phase 2: inverse T (parity) + ReLU + packed f32x2 channel mix; warp per y-line
    {
        int wid = tid >> 5, lane = tid & 31;
        for (int yi = wid; yi < 64; yi += 16) {
            float aE[16], aO[16];
#pragma unroll
            for (int c = 0; c < 16; c++) { aE[c] = 0.f; aO[c] = 0.f; }
#pragma unroll
            for (int k = 0; k < 12; k++) {
                float2 ab = sTi[k*32 + lane];
#pragma unroll
                for (int c = 0; c < 16; c++) {
                    float2 f = sF[(c*64 + yi)*13 + k];     // warp-uniform broadcast
                    float v = f.x*ab.x + f.y*ab.y;
                    if (k & 1) aO[c] += v; else aE[c] += v;
                }
            }
            unsigned long long p[16];
#pragma unroll
            for (int c = 0; c < 16; c++) {
                p[c] = pk2(fmaxf(aE[c] + aO[c], 0.f),      // t = lane
                           fmaxf(aE[c] - aO[c], 0.f));     // t = lane + 32
            }
#pragma unroll
            for (int o = 0; o < 16; o++) {
                unsigned long long acc = pk2(sB[o], sB[o]);
#pragma unroll
                for (int c = 0; c < 16; c++) fma2(acc, sWq[o*16 + c], p[c]);
                float2 rr = unpk2(acc);
                float* dst = out + ((((size_t)(b*16 + o)*64 + xx)*64 + yi)*64);
                dst[lane]      = rr.x;
                dst[lane + 32] = rr.y;
            }
        }
    }
}

// ---------------- launch ----------------
extern "C" void kernel_launch(void* const* d_in, const int* in_sizes, int n_in,
                              void* d_out, int out_size) {
    const float* x    = (const float*)d_in[0];
    const float* w1   = (const float*)d_in[1];
    const float* w2   = (const float*)d_in[2];
    const float* w3   = (const float*)d_in[3];
    const float* w4   = (const float*)d_in[4];
    const float* lo_w = (const float*)d_in[5];
    const float* lo_b = (const float*)d_in[6];
    float* out = (float*)d_out;

    cudaFuncSetAttribute(kD, cudaFuncAttributeMaxDynamicSharedMemorySize, KD_SMEM);

    k_init<<<5, 256>>>();
    k_repack<<<6912, 256>>>(w1, w2, w3, w4);
    kA<<<8192, 128>>>(x);                      // T 64->12, Y 64->24 (fused, radix-2)
    kB<<<2304, 384>>>();                       // X 64->24 + per-mode channel mix (radix-2)
    kC<<<3072, 384>>>();                       // X 24->64 (parity decimation)
    kD<<<512, KD_THREADS, KD_SMEM>>>(lo_w, lo_b, out);  // Y 24->64, T 12->64, relu, 1x1 conv
}

// round 3
// speedup vs baseline: 1.7751x; 1.7751x over previous
#include <cuda_runtime.h>
#include <math.h>

#define BATCH 8
#define CHN   16
#define NN    64
#define KT    12
#define KXY   24
#define N3INV (1.0f/262144.0f)

// ---------------- scratch (static device memory; no allocations) ----------------
__device__ float2 g_A [BATCH*CHN*NN*NN*KT];     // 50 MB: fwd T-DFT out; reused as inv-Y out
__device__ float2 g_Bf[BATCH*CHN*NN*KXY*KT];    // 19 MB: fwd Y-DFT out; reused as inv-X out
__device__ float2 g_D [BATCH*CHN*KXY*KXY*KT];   //  7 MB: spectral-multiplied modes
__device__ float2 g_W [KXY*KXY*KT*CHN*CHN];     // 14 MB: repacked weights, mode-major
__device__ float2 g_twT2 [KT*32];               // fwd T twiddle over t1<32
__device__ float2 g_twXY2[KXY*32];              // X/Y twiddle (24 kept freqs) over 32
__device__ float2 g_twTi2[KT*32];               // inv-T (A,B) with 1/N^3 and x2 folded

// ---------------- f32x2 packed helpers ----------------
__device__ __forceinline__ unsigned long long pk2(float lo, float hi){
    unsigned long long r; asm("mov.b64 %0, {%1,%2};" : "=l"(r) : "f"(lo), "f"(hi)); return r;
}
__device__ __forceinline__ void fma2(unsigned long long& d, unsigned long long a, unsigned long long b){
    asm("fma.rn.f32x2 %0, %1, %2, %0;" : "+l"(d) : "l"(a), "l"(b));
}
__device__ __forceinline__ float2 unpk2(unsigned long long v){
    float2 f; asm("mov.b64 {%0,%1}, %2;" : "=f"(f.x), "=f"(f.y) : "l"(v)); return f;
}

// ---------------- init: twiddle tables ----------------
__global__ void k_init() {
    int idx = blockIdx.x * blockDim.x + threadIdx.x;
    if (idx < 384) {
        int k = idx >> 5, t = idx & 31;
        int m = (k * t) & 63;
        float s, c;
        sincospif((float)m / 32.0f, &s, &c);
        g_twT2[idx] = make_float2(c, s);
        g_twTi2[idx] = (k == 0) ? make_float2(N3INV, 0.0f)
                                : make_float2(2.0f*c*N3INV, -2.0f*s*N3INV);
    } else if (idx < 384 + 768) {
        int r = idx - 384;
        int j = r >> 5, t = r & 31;
        int f = (j < 12) ? j : j + 40;   // freqs 0..11, 52..63
        int m = (f * t) & 63;
        float s, c;
        sincospif((float)m / 32.0f, &s, &c);
        g_twXY2[r] = make_float2(c, s);
    }
}

// ---------------- repack: register transpose, coalesced both sides ----------------
// block = (jx, jy); thread = (i,o); 4 quadrants sequentially
__global__ void __launch_bounds__(256) k_repack2(const float* __restrict__ w1, const float* __restrict__ w2,
                                                 const float* __restrict__ w3, const float* __restrict__ w4) {
    int jx = blockIdx.x / 12, jy = blockIdx.x % 12;
    int tid = threadIdx.x;
#pragma unroll
    for (int q = 0; q < 4; q++) {
        const float* w = (q == 0) ? w1 : (q == 1) ? w2 : (q == 2) ? w3 : w4;
        const float4* src = (const float4*)(w + ((size_t)tid*1728 + (jx*12 + jy)*12)*2);
        float2 r[12];
#pragma unroll
        for (int j = 0; j < 6; j++) {
            float4 v = src[j];
            r[2*j]   = make_float2(v.x, v.y);
            r[2*j+1] = make_float2(v.z, v.w);
        }
        int kxi = jx + ((q & 1) ? 12 : 0);   // q1,q3 -> kx high half
        int kyi = jy + ((q & 2) ? 12 : 0);   // q2,q3 -> ky high half
        float2* dst = g_W + ((size_t)(kxi*24 + kyi)*12)*256 + tid;
#pragma unroll
        for (int j = 0; j < 12; j++) dst[j*256] = r[j];
    }
}

// ---------------- K1: real DFT over T (radix-2, 64 -> 12 bins) ----------------
// block = 2 slabs of (b,c,x); 256 threads
__global__ void __launch_bounds__(256) k_dft_t(const float* __restrict__ x) {
    __shared__ float  s[2*NN*65];
    __shared__ float2 stw[KT*32];
    int slab0 = blockIdx.x * 2;
    const float4* xs = (const float4*)(x + (size_t)slab0 * 4096);
    for (int i = threadIdx.x; i < 2048; i += 256) {
        float4 v = xs[i];
        int sl = i >> 10, r = i & 1023;
        int yy = r >> 4, t4 = (r & 15) * 4;
        float* row = &s[sl*4160 + yy*65 + t4];
        row[0] = v.x; row[1] = v.y; row[2] = v.z; row[3] = v.w;
    }
    for (int i = threadIdx.x; i < 384; i += 256) stw[i] = g_twT2[i];
    __syncthreads();

    // radix-2 prep over t: E at [t1], O at [t1+32]
    for (int i = threadIdx.x; i < 4096; i += 256) {
        int sl = i >> 11, r = i & 2047;
        int yy = r >> 5, t1 = r & 31;
        float* row = &s[sl*4160 + yy*65];
        float a = row[t1], b = row[t1 + 32];
        row[t1] = a + b;  row[t1 + 32] = a - b;
    }
    __syncthreads();

    int sl   = threadIdx.x >> 7;
    int tloc = threadIdx.x & 127;
    int yy   = tloc & 63;
    int kb   = (tloc >> 6) * 6;           // kz base: 0 or 6 (warp-uniform)
    const float* row = &s[sl*4160 + yy*65];
    float ar[6], ai[6];
#pragma unroll
    for (int j = 0; j < 6; j++) { ar[j] = 0.f; ai[j] = 0.f; }
#pragma unroll 4
    for (int t1 = 0; t1 < 32; t1++) {
        float E = row[t1], O = row[t1 + 32];
#pragma unroll
        for (int j = 0; j < 6; j++) {
            int k = kb + j;
            float v = (k & 1) ? O : E;
            float2 w = stw[k*32 + t1];     // warp-uniform -> broadcast
            ar[j] += v * w.x;
            ai[j] -= v * w.y;
        }
    }
    float2* dst = g_A + (size_t)(slab0 + sl)*768 + yy*12 + kb;
#pragma unroll
    for (int j = 0; j < 6; j++) dst[j] = make_float2(ar[j], ai[j]);
}

// ---------------- K2: complex DFT over Y (radix-2, 64 -> 24 bins) ----------------
// block = 2 slabs; 288 threads; thread = (slab, ky, kz-pair)
__global__ void __launch_bounds__(288) k_dft_y() {
    __shared__ float2 sA[2*768];
    __shared__ float2 stw[KXY*32];
    int slab0 = blockIdx.x * 2;
    for (int i = threadIdx.x; i < 1536; i += 288) sA[i] = g_A[(size_t)slab0*768 + i];
    for (int i = threadIdx.x; i < 768; i += 288) stw[i] = g_twXY2[i];
    __syncthreads();

    // radix-2 prep over y: E at row y1, O at row y1+32 (r = y1*12+k)
    for (int i = threadIdx.x; i < 768; i += 288) {
        int sl = i / 384, r = i % 384;
        float2 a = sA[sl*768 + r], b = sA[sl*768 + 384 + r];
        sA[sl*768 + r]       = make_float2(a.x + b.x, a.y + b.y);
        sA[sl*768 + 384 + r] = make_float2(a.x - b.x, a.y - b.y);
    }
    __syncthreads();

    int sl   = threadIdx.x / 144;
    int tloc = threadIdx.x % 144;
    int ky = tloc / 6;
    int k0 = (tloc % 6) * 2;
    const float2* rowp = &sA[sl*768 + (ky & 1)*384 + k0];
    const float2* tw = &stw[ky*32];
    float2 acc0 = make_float2(0.f, 0.f), acc1 = make_float2(0.f, 0.f);
#pragma unroll 4
    for (int y1 = 0; y1 < 32; y1++) {
        float2 w = tw[y1];
        float2 a = rowp[y1*12];
        float2 b = rowp[y1*12 + 1];
        acc0.x += a.x*w.x + a.y*w.y;  acc0.y += a.y*w.x - a.x*w.y;   // * e^{-i th}
        acc1.x += b.x*w.x + b.y*w.y;  acc1.y += b.y*w.x - b.x*w.y;
    }
    float2* dst = g_Bf + (size_t)(slab0 + sl)*288 + ky*12 + k0;
    dst[0] = acc0; dst[1] = acc1;
}

// ---------------- KB: X-DFT (radix-2, 64->24) fused with spectral 16x16 mix ----------------
// block = (b, ky, kz); 384 threads
__global__ void __launch_bounds__(384) kB() {
    __shared__ float2 sIn[CHN*65];
    __shared__ float2 sAcc[KXY*CHN];
    __shared__ float2 stX[KXY*32];
    int blk = blockIdx.x;
    int b  = blk / 288;
    int r  = blk % 288;
    int ky = r / 12, kz = r % 12;
    int tid = threadIdx.x;

    for (int i = tid; i < 1024; i += 384) {
        int c = i >> 6, xx = i & 63;
        sIn[c*65 + xx] = g_Bf[(((size_t)(b*16 + c)*64 + xx)*24 + ky)*12 + kz];
    }
    for (int i = tid; i < 768; i += 384) stX[i] = g_twXY2[i];
    __syncthreads();

    for (int i = tid; i < 512; i += 384) {
        int c = i >> 5, x1 = i & 31;
        float2 a = sIn[c*65 + x1], bb = sIn[c*65 + x1 + 32];
        sIn[c*65 + x1]      = make_float2(a.x + bb.x, a.y + bb.y);
        sIn[c*65 + x1 + 32] = make_float2(a.x - bb.x, a.y - bb.y);
    }
    __syncthreads();

    {   // stage 1: X DFT -> sAcc[kx][c]
        int kx = tid >> 4, c = tid & 15;
        const float2* rowp = &sIn[c*65 + (kx & 1)*32];
        const float2* tw = &stX[kx*32];
        float2 acc = make_float2(0.f, 0.f);
#pragma unroll 4
        for (int x1 = 0; x1 < 32; x1++) {
            float2 w = tw[x1]; float2 v = rowp[x1];
            acc.x += v.x*w.x + v.y*w.y;
            acc.y += v.y*w.x - v.x*w.y;
        }
        sAcc[kx*16 + c] = acc;
    }
    __syncthreads();
    {   // stage 2: per-mode complex channel mix
        int kx = tid >> 4, o = tid & 15;
        const float2* Wp = g_W + ((size_t)((kx*24 + ky)*12 + kz)) * 256;
        float2 acc = make_float2(0.f, 0.f);
#pragma unroll
        for (int i = 0; i < 16; i++) {
            float2 av = sAcc[kx*16 + i];
            float2 w  = Wp[i*16 + o];
            acc.x += av.x*w.x - av.y*w.y;
            acc.y += av.x*w.y + av.y*w.x;
        }
        g_D[(((size_t)(b*16 + o)*24 + ky)*24 + kx)*12 + kz] = acc;
    }
}

// ---------------- KC: inverse X DFT (24 -> 64), parity decimation ----------------
// block = (bo, ky); 384 threads; thread = (kz, x1)
__global__ void __launch_bounds__(384) kC() {
    __shared__ float2 sD[KXY*KT];
    __shared__ float2 stX[KXY*32];
    int blk = blockIdx.x;              // bo*24 + ky
    int tid = threadIdx.x;
    for (int i = tid; i < 288; i += 384) sD[i] = g_D[(size_t)blk*288 + i];
    for (int i = tid; i < 768; i += 384) stX[i] = g_twXY2[i];
    __syncthreads();

    int kz = tid >> 5, x1 = tid & 31;
    float2 Se = make_float2(0.f, 0.f), So = make_float2(0.f, 0.f);
#pragma unroll
    for (int kx = 0; kx < 24; kx++) {
        float2 w = stX[kx*32 + x1];
        float2 d = sD[kx*12 + kz];
        float tr = d.x*w.x - d.y*w.y;    // * e^{+i th}
        float ti = d.x*w.y + d.y*w.x;
        if (kx & 1) { So.x += tr; So.y += ti; }
        else        { Se.x += tr; Se.y += ti; }
    }
    int bo = blk / 24, ky = blk % 24;
    float2* base = g_Bf + ((size_t)bo*64)*288 + ky*12 + kz;
    base[(size_t)x1*288]      = make_float2(Se.x + So.x, Se.y + So.y);
    base[(size_t)(x1+32)*288] = make_float2(Se.x - So.x, Se.y - So.y);
}

// ---------------- KYI: inverse Y DFT (24 -> 64), parity decimation ----------------
// block = (bo, x); 384 threads; thread = (kz, y1)
__global__ void __launch_bounds__(384) k_idft_y2() {
    __shared__ float2 sE[KXY*KT];
    __shared__ float2 stY[KXY*32];
    int blk = blockIdx.x;              // bo*64 + xx
    int tid = threadIdx.x;
    for (int i = tid; i < 288; i += 384) sE[i] = g_Bf[(size_t)blk*288 + i];
    for (int i = tid; i < 768; i += 384) stY[i] = g_twXY2[i];
    __syncthreads();

    int kz = tid >> 5, y1 = tid & 31;
    float2 Se = make_float2(0.f, 0.f), So = make_float2(0.f, 0.f);
#pragma unroll
    for (int ky = 0; ky < 24; ky++) {
        float2 w = stY[ky*32 + y1];
        float2 d = sE[ky*12 + kz];
        float tr = d.x*w.x - d.y*w.y;
        float ti = d.x*w.y + d.y*w.x;
        if (ky & 1) { So.x += tr; So.y += ti; }
        else        { Se.x += tr; Se.y += ti; }
    }
    float2* base = g_A + (size_t)blk*768 + kz;
    base[y1*12]        = make_float2(Se.x + So.x, Se.y + So.y);
    base[(y1 + 32)*12] = make_float2(Se.x - So.x, Se.y - So.y);
}

// ---------------- K7: inverse rfft over T (parity) + ReLU + packed 16x16 mix ----------------
// block = (b, x, y-group-of-8); 256 threads; one warp per y line; lane owns t and t+32
__global__ void __launch_bounds__(256) k_ifft_t_mix(const float* __restrict__ lo_w,
                                                    const float* __restrict__ lo_b,
                                                    float* __restrict__ out) {
    __shared__ float2 sF[8*CHN*KT];    // [slab][c][k]
    __shared__ float2 sTi[KT*32];
    __shared__ unsigned long long sWq[256];
    __shared__ float sB[16];
    int blk = blockIdx.x;              // (b*64+xx)*8 + ygrp
    int b   = blk >> 9;
    int rr  = blk & 511;
    int xx  = rr >> 3;
    int yy0 = (rr & 7) * 8;

    for (int i = threadIdx.x; i < 1536; i += 256) {
        int sl = i / 192, r2 = i % 192;
        int c = r2 / 12, k = r2 % 12;
        sF[i] = g_A[((((size_t)(b*16 + c)*64 + xx)*64) + yy0 + sl)*12 + k];
    }
    for (int i = threadIdx.x; i < 384; i += 256) sTi[i] = g_twTi2[i];
    if (threadIdx.x < 256) { float w = lo_w[threadIdx.x]; sWq[threadIdx.x] = pk2(w, w); }
    if (threadIdx.x < 16)  sB[threadIdx.x] = lo_b[threadIdx.x];
    __syncthreads();

    int w    = threadIdx.x >> 5;
    int lane = threadIdx.x & 31;
    int yy   = yy0 + w;
    const float2* F = &sF[w*192];

    float aE[CHN], aO[CHN];
#pragma unroll
    for (int c = 0; c < 16; c++) { aE[c] = 0.f; aO[c] = 0.f; }
#pragma unroll
    for (int k = 0; k < 12; k++) {
        float2 ab = sTi[k*32 + lane];
#pragma unroll
        for (int c = 0; c < 16; c++) {
            float2 f = F[c*12 + k];                 // warp-uniform broadcast
            float v = f.x*ab.x + f.y*ab.y;          // 2 Re(F e^{i th})/N^3
            if (k & 1) aO[c] += v; else aE[c] += v;
        }
    }
    unsigned long long p[CHN];
#pragma unroll
    for (int c = 0; c < 16; c++) {
        p[c] = pk2(fmaxf(aE[c] + aO[c], 0.f),       // t = lane
                   fmaxf(aE[c] - aO[c], 0.f));      // t = lane + 32
    }
#pragma unroll
    for (int o = 0; o < 16; o++) {
        unsigned long long acc = pk2(sB[o], sB[o]);
#pragma unroll
        for (int c = 0; c < 16; c++) fma2(acc, sWq[o*16 + c], p[c]);
        float2 rv = unpk2(acc);
        float* dst = out + ((((size_t)(b*16 + o)*64 + xx)*64 + yy)*64);
        dst[lane]      = rv.x;
        dst[lane + 32] = rv.y;
    }
}

// ---------------- launch ----------------
extern "C" void kernel_launch(void* const* d_in, const int* in_sizes, int n_in,
                              void* d_out, int out_size) {
    const float* x    = (const float*)d_in[0];
    const float* w1   = (const float*)d_in[1];
    const float* w2   = (const float*)d_in[2];
    const float* w3   = (const float*)d_in[3];
    const float* w4   = (const float*)d_in[4];
    const float* lo_w = (const float*)d_in[5];
    const float* lo_b = (const float*)d_in[6];
    float* out = (float*)d_out;

    k_init<<<5, 256>>>();
    k_repack2<<<144, 256>>>(w1, w2, w3, w4);
    k_dft_t<<<4096, 256>>>(x);                       // T 64->12 (radix-2)
    k_dft_y<<<4096, 288>>>();                        // Y 64->24 (radix-2)
    kB<<<2304, 384>>>();                             // X 64->24 + channel mix (radix-2)
    kC<<<3072, 384>>>();                             // X 24->64 (parity)
    k_idft_y2<<<8192, 384>>>();                      // Y 24->64 (parity)
    k_ifft_t_mix<<<4096, 256>>>(lo_w, lo_b, out);    // T 12->64 (parity) + relu + 1x1 conv
}